// round 12
// baseline (speedup 1.0000x reference)
#include <cuda_runtime.h>

#define DD 512
#define BB 128
#define EPSF 1e-5f
#define LOG2E_F 1.4426950408889634f
#define TJ 64                    // j-tile width in k_main

// scratch (static device memory — no allocations)
__device__ float g_wk[3 * BB * DD];
__device__ float g_wq[3 * BB * DD];
__device__ float g_y [3 * BB * DD];
__device__ float g_wt[3 * DD * DD];   // transposed Wk, Wq, fc_w

struct Ptr3 { const float* p[3]; };

__device__ __forceinline__ float ex2f(float x) {
    float y;
    asm("ex2.approx.ftz.f32 %0, %1;" : "=f"(y) : "f"(x));
    return y;
}

// ===================== transpose: g_wt[z][d][m] = W_z[m][d] =====================
__global__ void __launch_bounds__(256)
k_transpose(const float* __restrict__ W0, const float* __restrict__ W1,
            const float* __restrict__ W2)
{
    __shared__ float t[32][33];
    const float* W = (blockIdx.z == 0) ? W0 : (blockIdx.z == 1) ? W1 : W2;
    float* O = g_wt + (size_t)blockIdx.z * DD * DD;
    int x  = blockIdx.x * 32 + threadIdx.x;
    int y0 = blockIdx.y * 32;
    #pragma unroll
    for (int i = threadIdx.y; i < 32; i += 8)
        t[i][threadIdx.x] = W[(size_t)(y0 + i) * DD + x];
    __syncthreads();
    int xo  = blockIdx.y * 32 + threadIdx.x;
    int yo0 = blockIdx.x * 32;
    #pragma unroll
    for (int i = threadIdx.y; i < 32; i += 8)
        O[(size_t)(yo0 + i) * DD + xo] = t[threadIdx.x][i];
}

// ===================== GEMM v11: 4r x 32c tile, K-split 16 in-block =====================
// out[row, m] = sum_d src[row, d] * Wt[d, m] + bias[m] (+ residual src)
// block = 128 threads; c4 = tid&7 (8 col-quads -> 32 cols), dq = tid>>3 (16 chunks of 32 k)
// grid: (96 row-tiles, 16 col-tiles, Z)
struct GemmArgs {
    Ptr3 src[2];
    const float* bias[2];
    float* out[2];
    int wtsel[2];
};

template <bool RES>
__global__ void __launch_bounds__(128)
k_gemm11(GemmArgs ga)
{
    __shared__ __align__(16) float  sm_src[4 * DD];        // 8 KB
    __shared__ __align__(16) float4 sm_red[16][4][8];      // 8 KB

    int z  = blockIdx.z;
    int rt = blockIdx.x;
    int cc = blockIdx.y;
    int tid = threadIdx.x;

    int c  = (rt * 4) / BB;
    int b0 = (rt * 4) % BB;
    const float* s  = ga.src[z].p[c] + (size_t)b0 * DD;
    const float* Wt = g_wt + (size_t)ga.wtsel[z] * DD * DD + cc * 32;

    #pragma unroll
    for (int i = tid; i < 4 * DD / 4; i += 128)
        ((float4*)sm_src)[i] = ((const float4*)s)[i];
    __syncthreads();

    int c4 = tid & 7;      // 8 col-quads -> 32 cols
    int dq = tid >> 3;     // 16 d-chunks of 32
    const float4* wp = (const float4*)(Wt + (size_t)dq * 32 * DD) + c4;
    const float*  sb = sm_src + dq * 32;

    float4 acc[4];
    #pragma unroll
    for (int r = 0; r < 4; r++) acc[r] = make_float4(0.f, 0.f, 0.f, 0.f);

    #pragma unroll 2
    for (int dd = 0; dd < 32; dd += 4) {
        float4 w0 = wp[(dd + 0) * (DD / 4)];
        float4 w1 = wp[(dd + 1) * (DD / 4)];
        float4 w2 = wp[(dd + 2) * (DD / 4)];
        float4 w3 = wp[(dd + 3) * (DD / 4)];
        #pragma unroll
        for (int r = 0; r < 4; r++) {
            float4 s4 = *(const float4*)(sb + r * DD + dd);  // broadcast LDS
            acc[r].x = fmaf(s4.x, w0.x, fmaf(s4.y, w1.x, fmaf(s4.z, w2.x, fmaf(s4.w, w3.x, acc[r].x))));
            acc[r].y = fmaf(s4.x, w0.y, fmaf(s4.y, w1.y, fmaf(s4.z, w2.y, fmaf(s4.w, w3.y, acc[r].y))));
            acc[r].z = fmaf(s4.x, w0.z, fmaf(s4.y, w1.z, fmaf(s4.z, w2.z, fmaf(s4.w, w3.z, acc[r].z))));
            acc[r].w = fmaf(s4.x, w0.w, fmaf(s4.y, w1.w, fmaf(s4.z, w2.w, fmaf(s4.w, w3.w, acc[r].w))));
        }
    }

    #pragma unroll
    for (int r = 0; r < 4; r++)
        sm_red[dq][r][c4] = acc[r];
    __syncthreads();

    if (tid < 32) {
        int r  = tid >> 3;
        int cq = tid & 7;
        float4 sum = sm_red[0][r][cq];
        #pragma unroll
        for (int q = 1; q < 16; q++) {
            float4 v = sm_red[q][r][cq];
            sum.x += v.x; sum.y += v.y; sum.z += v.z; sum.w += v.w;
        }
        int col = cc * 32 + cq * 4;
        float4 bb = *(const float4*)(ga.bias[z] + col);
        sum.x += bb.x; sum.y += bb.y; sum.z += bb.z; sum.w += bb.w;
        if (RES) {
            float4 yv = *(const float4*)(sm_src + r * DD + col);
            sum.x += yv.x; sum.y += yv.y; sum.z += yv.z; sum.w += yv.w;
        }
        *(float4*)(ga.out[z] + (size_t)(rt * 4 + r) * DD + col) = sum;
    }
}

// ---- block reductions over 512 threads (16 warps) ----
__device__ __forceinline__ float blockReduceSum(float v, float* red) {
    int tid = threadIdx.x, lane = tid & 31, wid = tid >> 5;
    #pragma unroll
    for (int o = 16; o > 0; o >>= 1) v += __shfl_down_sync(0xffffffffu, v, o);
    if (lane == 0) red[wid] = v;
    __syncthreads();
    if (wid == 0) {
        float x = (lane < 16) ? red[lane] : 0.0f;
        #pragma unroll
        for (int o = 8; o > 0; o >>= 1) x += __shfl_down_sync(0xffffffffu, x, o);
        if (lane == 0) red[0] = x;
    }
    __syncthreads();
    float r = red[0];
    __syncthreads();
    return r;
}

__device__ __forceinline__ float blockReduceMax(float v, float* red) {
    int tid = threadIdx.x, lane = tid & 31, wid = tid >> 5;
    #pragma unroll
    for (int o = 16; o > 0; o >>= 1) v = fmaxf(v, __shfl_down_sync(0xffffffffu, v, o));
    if (lane == 0) red[wid] = v;
    __syncthreads();
    if (wid == 0) {
        float x = (lane < 16) ? red[lane] : -3.4e38f;
        #pragma unroll
        for (int o = 8; o > 0; o >>= 1) x = fmaxf(x, __shfl_down_sync(0xffffffffu, x, o));
        if (lane == 0) red[0] = x;
    }
    __syncthreads();
    float r = red[0];
    __syncthreads();
    return r;
}

__device__ __forceinline__ float blockReduceMin(float v, float* red) {
    int tid = threadIdx.x, lane = tid & 31, wid = tid >> 5;
    #pragma unroll
    for (int o = 16; o > 0; o >>= 1) v = fminf(v, __shfl_down_sync(0xffffffffu, v, o));
    if (lane == 0) red[wid] = v;
    __syncthreads();
    if (wid == 0) {
        float x = (lane < 16) ? red[lane] : 3.4e38f;
        #pragma unroll
        for (int o = 8; o > 0; o >>= 1) x = fminf(x, __shfl_down_sync(0xffffffffu, x, o));
        if (lane == 0) red[0] = x;
    }
    __syncthreads();
    float r = red[0];
    __syncthreads();
    return r;
}

// ---- main fused kernel: one block per (batch, channel), TJ=64 tiles ----
__global__ void __launch_bounds__(512)
k_main(Ptr3 x, Ptr3 h, Ptr3 kq,
       const float* __restrict__ kn_g, const float* __restrict__ kn_b,
       const float* __restrict__ norm_g, const float* __restrict__ norm_b)
{
    extern __shared__ float E[];              // [512][TJ+1], odd stride -> conflict-free
    __shared__ float s_s[DD], s_u2[DD], s_v[DD];
    __shared__ float Zpart[8][TJ + 1];
    __shared__ float coefT[TJ];
    __shared__ float red[32];

    const int ESTR = TJ + 1;

    int b = blockIdx.x, c = blockIdx.y, tid = threadIdx.x;
    int row = c * BB + b;

    float wk = g_wk[(size_t)row * DD + tid];
    float wq = g_wq[(size_t)row * DD + tid];
    float kv = h.p[c][(size_t)b * DD + tid];
    float qv = kq.p[c][(size_t)b * DD + tid];
    float vv = x.p[c][(size_t)b * DD + tid];

    const float inv_d = 1.0f / (float)DD;
    float mu_wk  = blockReduceSum(wk, red) * inv_d;
    float dk     = wk - mu_wk;
    float var_wk = blockReduceSum(dk * dk, red) * inv_d;
    float mu_wq  = blockReduceSum(wq, red) * inv_d;
    float dq     = wq - mu_wq;
    float var_wq = blockReduceSum(dq * dq, red) * inv_d;

    float gg = kn_g[tid];
    float cb = kn_b[tid];

    float si = kv * rsqrtf(kv * kv * var_wk + EPSF);
    float ti = qv * rsqrtf(qv * qv * var_wq + EPSF);
    float Ai = dk * gg;
    float Bi = dq * gg;

    float P    = blockReduceSum(Ai * ti, red);
    float Qs   = blockReduceSum(Ai, red);
    float smax = blockReduceMax(si, red);
    float smin = blockReduceMin(si, red);

    float u2 = (P * Bi + Qs * cb) * LOG2E_F;
    s_s[tid]  = si;
    s_u2[tid] = u2;
    s_v[tid]  = vv;
    __syncthreads();

    int g = tid >> 6;          // 8 i-groups of 64 rows
    int j = tid & 63;          // column within tile

    float acc = 0.0f;

    #pragma unroll 1
    for (int jt = 0; jt < DD; jt += TJ) {
        float u2j = s_u2[jt + j];
        float m2j = fmaxf(u2j * smax, u2j * smin);
        float Zl = 0.0f;

        float* Ecol = E + (size_t)(g * 64) * ESTR + j;
        const float* sbase = s_s + g * 64;
        #pragma unroll
        for (int i4 = 0; i4 < 64; i4 += 4) {
            float4 s4 = *(const float4*)(sbase + i4);    // broadcast LDS
            float e0 = ex2f(fmaf(s4.x, u2j, -m2j));
            float e1 = ex2f(fmaf(s4.y, u2j, -m2j));
            float e2 = ex2f(fmaf(s4.z, u2j, -m2j));
            float e3 = ex2f(fmaf(s4.w, u2j, -m2j));
            Zl += (e0 + e1) + (e2 + e3);
            Ecol[(i4 + 0) * ESTR] = e0;
            Ecol[(i4 + 1) * ESTR] = e1;
            Ecol[(i4 + 2) * ESTR] = e2;
            Ecol[(i4 + 3) * ESTR] = e3;
        }
        Zpart[g][j] = Zl;
        __syncthreads();

        if (tid < TJ) {
            float zt = 0.0f;
            #pragma unroll
            for (int w = 0; w < 8; w++) zt += Zpart[w][tid];
            coefT[tid] = s_v[jt + tid] / zt;
        }
        __syncthreads();

        const float* Erow = E + (size_t)tid * ESTR;
        #pragma unroll
        for (int jj = 0; jj < TJ; jj += 4) {
            float c0 = coefT[jj + 0], c1 = coefT[jj + 1];
            float c2 = coefT[jj + 2], c3 = coefT[jj + 3];
            acc = fmaf(c0, Erow[jj + 0], acc);
            acc = fmaf(c1, Erow[jj + 1], acc);
            acc = fmaf(c2, Erow[jj + 2], acc);
            acc = fmaf(c3, Erow[jj + 3], acc);
        }
        __syncthreads();     // E reused next tile
    }

    float y     = acc + vv;
    float mu_y  = blockReduceSum(y, red) * inv_d;
    float dy    = y - mu_y;
    float var_y = blockReduceSum(dy * dy, red) * inv_d;
    float yn    = dy * rsqrtf(var_y + EPSF) * norm_g[tid] + norm_b[tid];

    g_y[(size_t)row * DD + tid] = yn;
}

extern "C" void kernel_launch(void* const* d_in, const int* in_sizes, int n_in,
                              void* d_out, int out_size)
{
    (void)in_sizes; (void)n_in; (void)out_size;
    const float* r    = (const float*)d_in[0];
    const float* g    = (const float*)d_in[1];
    const float* b    = (const float*)d_in[2];
    const float* h_r  = (const float*)d_in[3];
    const float* h_g  = (const float*)d_in[4];
    const float* h_b  = (const float*)d_in[5];
    const float* k_r  = (const float*)d_in[6];
    const float* k_g  = (const float*)d_in[7];
    const float* k_b  = (const float*)d_in[8];
    const float* Wk   = (const float*)d_in[9];
    const float* bk   = (const float*)d_in[10];
    const float* Wq   = (const float*)d_in[11];
    const float* bq   = (const float*)d_in[12];
    const float* kn_g = (const float*)d_in[13];
    const float* kn_b = (const float*)d_in[14];
    const float* norm_g = (const float*)d_in[15];
    const float* norm_b = (const float*)d_in[16];
    const float* fc_w = (const float*)d_in[17];
    const float* fc_b = (const float*)d_in[18];
    float* out = (float*)d_out;

    Ptr3 X  = {{ r,   g,   b   }};
    Ptr3 H  = {{ h_r, h_g, h_b }};
    Ptr3 KQ = {{ k_r, k_g, k_b }};

    const size_t E_BYTES = (size_t)DD * (TJ + 1) * sizeof(float);   // 133 KB

    static float* wk_dev = nullptr;
    static float* wq_dev = nullptr;
    static float* y_dev  = nullptr;
    if (y_dev == nullptr) {
        void* p = nullptr;
        cudaGetSymbolAddress(&p, g_y);  y_dev  = (float*)p;
        cudaGetSymbolAddress(&p, g_wk); wk_dev = (float*)p;
        cudaGetSymbolAddress(&p, g_wq); wq_dev = (float*)p;
        cudaFuncSetAttribute(k_main, cudaFuncAttributeMaxDynamicSharedMemorySize,
                             (int)E_BYTES);
    }

    // Stage 0: transpose Wk, Wq, fc_w into g_wt
    k_transpose<<<dim3(16, 16, 3), dim3(32, 8)>>>(Wk, Wq, fc_w);

    // Stage 1: w_k = h @ Wk.T + bk ; w_q = kidx @ Wq.T + bq  (z selects matrix)
    {
        GemmArgs ga;
        ga.src[0] = H;  ga.src[1] = KQ;
        ga.bias[0] = bk; ga.bias[1] = bq;
        ga.out[0] = wk_dev; ga.out[1] = wq_dev;
        ga.wtsel[0] = 0; ga.wtsel[1] = 1;
        k_gemm11<false><<<dim3(3 * BB / 4, 16, 2), 128>>>(ga);
    }

    // Stage 2: collapsed attention + residual + LN -> g_y
    k_main<<<dim3(BB, 3), 512, E_BYTES>>>(X, H, KQ, kn_g, kn_b, norm_g, norm_b);

    // Stage 3: out = y @ fc_w.T + fc_b + y
    {
        Ptr3 Y = {{ y_dev, y_dev + BB * DD, y_dev + 2 * BB * DD }};
        GemmArgs ga;
        ga.src[0] = Y;  ga.src[1] = Y;
        ga.bias[0] = fc_b; ga.bias[1] = fc_b;
        ga.out[0] = out; ga.out[1] = out;
        ga.wtsel[0] = 2; ga.wtsel[1] = 2;
        k_gemm11<true><<<dim3(3 * BB / 4, 16, 1), 128>>>(ga);
    }
}

// round 13
// speedup vs baseline: 1.1004x; 1.1004x over previous
#include <cuda_runtime.h>

#define DD 512
#define BB 128
#define EPSF 1e-5f
#define LOG2E_F 1.4426950408889634f
#define TJ 32
#define MATSZ (384 * 512)

// scratch (static device memory — no allocations)
__device__ float g_y [3 * BB * DD];
__device__ float g_wt[3 * DD * DD];     // k-major weights: [mat][k][m]
__device__ float g_part[8 * MATSZ];     // K-split partials

struct Ptr3 { const float* p[3]; };

__device__ __forceinline__ float ex2f(float x) {
    float y;
    asm("ex2.approx.ftz.f32 %0, %1;" : "=f"(y) : "f"(x));
    return y;
}

// ===================== transpose weights: g_wt[z][d][m] = W_z[m][d] =====================
__global__ void __launch_bounds__(256)
k_transpose(const float* __restrict__ W0, const float* __restrict__ W1,
            const float* __restrict__ W2)
{
    __shared__ float t[32][33];
    const float* W = (blockIdx.z == 0) ? W0 : (blockIdx.z == 1) ? W1 : W2;
    float* O = g_wt + (size_t)blockIdx.z * DD * DD;
    int x  = blockIdx.x * 32 + threadIdx.x;
    int y0 = blockIdx.y * 32;
    #pragma unroll
    for (int i = threadIdx.y; i < 32; i += 8)
        t[i][threadIdx.x] = W[(size_t)(y0 + i) * DD + x];
    __syncthreads();
    int xo  = blockIdx.y * 32 + threadIdx.x;
    int yo0 = blockIdx.x * 32;
    #pragma unroll
    for (int i = threadIdx.y; i < 32; i += 8)
        O[(size_t)(yo0 + i) * DD + xo] = t[threadIdx.x][i];
}

// ===================== GEMM v12: 16r x 128c tile, K-split 4, pure partials ==========
// g_part[z][row][col] = sum_{k in quarter} src[row][k] * Wt[k][col]
// block 128 thr; thread tile 4r x 4c (c4 = tid&31, rq = tid>>5); K = 128 per block.
// grid: (rowtiles=24, coltiles=4, z = mat*4 + ks). Weight re-read factor = 24 (vs 96 in R3).
struct GemmArgs {
    Ptr3 src[2];
    int wtsel[2];
};

#define KP 128   // K per block

__global__ void __launch_bounds__(128)
k_gemm12(GemmArgs ga)
{
    __shared__ __align__(16) float sm_src[16 * KP];   // 8 KB (k-slice of 16 rows)

    int tid = threadIdx.x;
    int rt = blockIdx.x, ct = blockIdx.y, z = blockIdx.z;
    int mat = z >> 2, ks = z & 3;
    int r0 = rt * 16;
    int c0 = ct * 128;
    int k0 = ks * KP;

    const float* src = ga.src[mat].p[r0 >> 7] + (size_t)(r0 & 127) * DD;
    const float* Wt  = g_wt + (size_t)ga.wtsel[mat] * DD * DD + (size_t)k0 * DD + c0;

    // stage the 16-row x 128-k source slice (coalesced)
    #pragma unroll
    for (int it = 0; it < 4; it++) {
        int idx = it * 128 + tid;
        int row = idx >> 5, q = idx & 31;
        *(float4*)&sm_src[row * KP + q * 4] =
            *(const float4*)(src + (size_t)row * DD + k0 + q * 4);
    }
    __syncthreads();

    int c4 = tid & 31;     // 32 col-quads -> 128 cols
    int rq = tid >> 5;     // 4 row-quads -> 16 rows
    const float* wbase = Wt + c4 * 4;
    const float* sb    = sm_src + rq * 4 * KP;

    float4 acc[4];
    #pragma unroll
    for (int r = 0; r < 4; r++) acc[r] = make_float4(0.f, 0.f, 0.f, 0.f);

    #pragma unroll 4
    for (int g = 0; g < 32; g++) {
        int kk = g * 4;
        float4 w0 = *(const float4*)(wbase + (size_t)(kk + 0) * DD);
        float4 w1 = *(const float4*)(wbase + (size_t)(kk + 1) * DD);
        float4 w2 = *(const float4*)(wbase + (size_t)(kk + 2) * DD);
        float4 w3 = *(const float4*)(wbase + (size_t)(kk + 3) * DD);
        #pragma unroll
        for (int r = 0; r < 4; r++) {
            float4 s4 = *(const float4*)(sb + r * KP + kk);   // broadcast LDS
            acc[r].x = fmaf(s4.x, w0.x, fmaf(s4.y, w1.x, fmaf(s4.z, w2.x, fmaf(s4.w, w3.x, acc[r].x))));
            acc[r].y = fmaf(s4.x, w0.y, fmaf(s4.y, w1.y, fmaf(s4.z, w2.y, fmaf(s4.w, w3.y, acc[r].y))));
            acc[r].z = fmaf(s4.x, w0.z, fmaf(s4.y, w1.z, fmaf(s4.z, w2.z, fmaf(s4.w, w3.z, acc[r].z))));
            acc[r].w = fmaf(s4.x, w0.w, fmaf(s4.y, w1.w, fmaf(s4.z, w2.w, fmaf(s4.w, w3.w, acc[r].w))));
        }
    }

    float* outp = g_part + (size_t)z * MATSZ;
    #pragma unroll
    for (int r = 0; r < 4; r++) {
        int row = r0 + rq * 4 + r;
        *(float4*)(outp + (size_t)row * DD + c0 + c4 * 4) = acc[r];
    }
}

// ===================== fc final reduce: out = p0..p3 + fc_b + y (float4) =====================
__global__ void __launch_bounds__(256)
k_reduce2(const float* __restrict__ fcb, float* __restrict__ out)
{
    int idx = blockIdx.x * 256 + threadIdx.x;        // float4 index, 49152 total
    size_t i = (size_t)idx * 4;
    int col = (idx & 127) * 4;
    float4 a = *(const float4*)(g_part + i);
    float4 b = *(const float4*)(g_part + MATSZ + i);
    float4 c = *(const float4*)(g_part + 2 * MATSZ + i);
    float4 d = *(const float4*)(g_part + 3 * MATSZ + i);
    float4 bb = *(const float4*)(fcb + col);
    float4 yy = *(const float4*)(g_y + i);
    float4 v;
    v.x = (a.x + b.x) + (c.x + d.x) + bb.x + yy.x;
    v.y = (a.y + b.y) + (c.y + d.y) + bb.y + yy.y;
    v.z = (a.z + b.z) + (c.z + d.z) + bb.z + yy.z;
    v.w = (a.w + b.w) + (c.w + d.w) + bb.w + yy.w;
    *(float4*)(out + i) = v;
}

// ---- block reductions over 512 threads (16 warps) ----
__device__ __forceinline__ float blockReduceSum(float v, float* red) {
    int tid = threadIdx.x, lane = tid & 31, wid = tid >> 5;
    #pragma unroll
    for (int o = 16; o > 0; o >>= 1) v += __shfl_down_sync(0xffffffffu, v, o);
    if (lane == 0) red[wid] = v;
    __syncthreads();
    if (wid == 0) {
        float x = (lane < 16) ? red[lane] : 0.0f;
        #pragma unroll
        for (int o = 8; o > 0; o >>= 1) x += __shfl_down_sync(0xffffffffu, x, o);
        if (lane == 0) red[0] = x;
    }
    __syncthreads();
    float r = red[0];
    __syncthreads();
    return r;
}

__device__ __forceinline__ float blockReduceMax(float v, float* red) {
    int tid = threadIdx.x, lane = tid & 31, wid = tid >> 5;
    #pragma unroll
    for (int o = 16; o > 0; o >>= 1) v = fmaxf(v, __shfl_down_sync(0xffffffffu, v, o));
    if (lane == 0) red[wid] = v;
    __syncthreads();
    if (wid == 0) {
        float x = (lane < 16) ? red[lane] : -3.4e38f;
        #pragma unroll
        for (int o = 8; o > 0; o >>= 1) x = fmaxf(x, __shfl_down_sync(0xffffffffu, x, o));
        if (lane == 0) red[0] = x;
    }
    __syncthreads();
    float r = red[0];
    __syncthreads();
    return r;
}

__device__ __forceinline__ float blockReduceMin(float v, float* red) {
    int tid = threadIdx.x, lane = tid & 31, wid = tid >> 5;
    #pragma unroll
    for (int o = 16; o > 0; o >>= 1) v = fminf(v, __shfl_down_sync(0xffffffffu, v, o));
    if (lane == 0) red[wid] = v;
    __syncthreads();
    if (wid == 0) {
        float x = (lane < 16) ? red[lane] : 3.4e38f;
        #pragma unroll
        for (int o = 8; o > 0; o >>= 1) x = fminf(x, __shfl_down_sync(0xffffffffu, x, o));
        if (lane == 0) red[0] = x;
    }
    __syncthreads();
    float r = red[0];
    __syncthreads();
    return r;
}

// ---- main fused kernel: one block per (batch, channel) ----
// Folds the stage-1 K-split-4 reduction + bias into its loads.
__global__ void __launch_bounds__(512)
k_main(Ptr3 x, Ptr3 h, Ptr3 kq,
       const float* __restrict__ bk, const float* __restrict__ bq,
       const float* __restrict__ kn_g, const float* __restrict__ kn_b,
       const float* __restrict__ norm_g, const float* __restrict__ norm_b)
{
    extern __shared__ float E[];              // [512][TJ+1]
    __shared__ float s_s[DD], s_u2[DD], s_v[DD];
    __shared__ float Zpart[16][TJ + 1];
    __shared__ float coefT[TJ];
    __shared__ float red[32];

    const int ESTR = TJ + 1;

    int b = blockIdx.x, c = blockIdx.y, tid = threadIdx.x;
    int row = c * BB + b;
    size_t ri = (size_t)row * DD + tid;

    float wk = ((g_part[ri] + g_part[MATSZ + ri])
              + (g_part[2 * MATSZ + ri] + g_part[3 * MATSZ + ri])) + bk[tid];
    float wq = ((g_part[4 * MATSZ + ri] + g_part[5 * MATSZ + ri])
              + (g_part[6 * MATSZ + ri] + g_part[7 * MATSZ + ri])) + bq[tid];
    float kv = h.p[c][(size_t)b * DD + tid];
    float qv = kq.p[c][(size_t)b * DD + tid];
    float vv = x.p[c][(size_t)b * DD + tid];

    const float inv_d = 1.0f / (float)DD;
    float mu_wk  = blockReduceSum(wk, red) * inv_d;
    float dk     = wk - mu_wk;
    float var_wk = blockReduceSum(dk * dk, red) * inv_d;
    float mu_wq  = blockReduceSum(wq, red) * inv_d;
    float dq     = wq - mu_wq;
    float var_wq = blockReduceSum(dq * dq, red) * inv_d;

    float gg = kn_g[tid];
    float cb = kn_b[tid];

    float si = kv * rsqrtf(kv * kv * var_wk + EPSF);
    float ti = qv * rsqrtf(qv * qv * var_wq + EPSF);
    float Ai = dk * gg;
    float Bi = dq * gg;

    float P    = blockReduceSum(Ai * ti, red);
    float Qs   = blockReduceSum(Ai, red);
    float smax = blockReduceMax(si, red);
    float smin = blockReduceMin(si, red);

    float u2 = (P * Bi + Qs * cb) * LOG2E_F;
    s_s[tid]  = si;
    s_u2[tid] = u2;
    s_v[tid]  = vv;
    __syncthreads();

    int g = tid >> 5;
    int j = tid & 31;

    float acc = 0.0f;

    #pragma unroll 1
    for (int jt = 0; jt < DD; jt += TJ) {
        float u2j = s_u2[jt + j];
        float m2j = fmaxf(u2j * smax, u2j * smin);
        float Zl = 0.0f;

        float* Ecol = E + (size_t)(g * 32) * ESTR + j;
        const float* sbase = s_s + g * 32;
        #pragma unroll
        for (int i4 = 0; i4 < 32; i4 += 4) {
            float4 s4 = *(const float4*)(sbase + i4);
            float e0 = ex2f(fmaf(s4.x, u2j, -m2j));
            float e1 = ex2f(fmaf(s4.y, u2j, -m2j));
            float e2 = ex2f(fmaf(s4.z, u2j, -m2j));
            float e3 = ex2f(fmaf(s4.w, u2j, -m2j));
            Zl += (e0 + e1) + (e2 + e3);
            Ecol[(i4 + 0) * ESTR] = e0;
            Ecol[(i4 + 1) * ESTR] = e1;
            Ecol[(i4 + 2) * ESTR] = e2;
            Ecol[(i4 + 3) * ESTR] = e3;
        }
        Zpart[g][j] = Zl;
        __syncthreads();

        if (tid < TJ) {
            float zt = 0.0f;
            #pragma unroll
            for (int w = 0; w < 16; w++) zt += Zpart[w][tid];
            coefT[tid] = s_v[jt + tid] / zt;
        }
        __syncthreads();

        const float* Erow = E + (size_t)tid * ESTR;
        #pragma unroll
        for (int jj = 0; jj < TJ; jj += 4) {
            float c0 = coefT[jj + 0], c1 = coefT[jj + 1];
            float c2 = coefT[jj + 2], c3 = coefT[jj + 3];
            acc = fmaf(c0, Erow[jj + 0], acc);
            acc = fmaf(c1, Erow[jj + 1], acc);
            acc = fmaf(c2, Erow[jj + 2], acc);
            acc = fmaf(c3, Erow[jj + 3], acc);
        }
        __syncthreads();
    }

    float y     = acc + vv;
    float mu_y  = blockReduceSum(y, red) * inv_d;
    float dy    = y - mu_y;
    float var_y = blockReduceSum(dy * dy, red) * inv_d;
    float yn    = dy * rsqrtf(var_y + EPSF) * norm_g[tid] + norm_b[tid];

    g_y[(size_t)row * DD + tid] = yn;
}

extern "C" void kernel_launch(void* const* d_in, const int* in_sizes, int n_in,
                              void* d_out, int out_size)
{
    (void)in_sizes; (void)n_in; (void)out_size;
    const float* r    = (const float*)d_in[0];
    const float* g    = (const float*)d_in[1];
    const float* b    = (const float*)d_in[2];
    const float* h_r  = (const float*)d_in[3];
    const float* h_g  = (const float*)d_in[4];
    const float* h_b  = (const float*)d_in[5];
    const float* k_r  = (const float*)d_in[6];
    const float* k_g  = (const float*)d_in[7];
    const float* k_b  = (const float*)d_in[8];
    const float* Wk   = (const float*)d_in[9];
    const float* bk   = (const float*)d_in[10];
    const float* Wq   = (const float*)d_in[11];
    const float* bq   = (const float*)d_in[12];
    const float* kn_g = (const float*)d_in[13];
    const float* kn_b = (const float*)d_in[14];
    const float* norm_g = (const float*)d_in[15];
    const float* norm_b = (const float*)d_in[16];
    const float* fc_w = (const float*)d_in[17];
    const float* fc_b = (const float*)d_in[18];
    float* out = (float*)d_out;

    Ptr3 X  = {{ r,   g,   b   }};
    Ptr3 H  = {{ h_r, h_g, h_b }};
    Ptr3 KQ = {{ k_r, k_g, k_b }};

    const size_t E_BYTES = (size_t)DD * (TJ + 1) * sizeof(float);

    static float* y_dev  = nullptr;
    if (y_dev == nullptr) {
        void* p = nullptr;
        cudaGetSymbolAddress(&p, g_y);  y_dev = (float*)p;
        cudaFuncSetAttribute(k_main, cudaFuncAttributeMaxDynamicSharedMemorySize,
                             (int)E_BYTES);
    }

    // Stage 0: transpose weights -> g_wt (k-major)
    k_transpose<<<dim3(16, 16, 3), dim3(32, 8)>>>(Wk, Wq, fc_w);

    // Stage 1: w_k / w_q partials (K-split 4 per matrix), z = mat*4 + ks
    {
        GemmArgs ga;
        ga.src[0] = H;  ga.src[1] = KQ;
        ga.wtsel[0] = 0; ga.wtsel[1] = 1;
        k_gemm12<<<dim3(24, 4, 8), 128>>>(ga);
    }

    // Stage 2: folds stage-1 partials + bias; attention + residual + LN -> g_y
    k_main<<<dim3(BB, 3), 512, E_BYTES>>>(X, H, KQ, bk, bq,
                                          kn_g, kn_b, norm_g, norm_b);

    // Stage 3: fc partials (K-split 4), src = g_y
    {
        Ptr3 Y = {{ y_dev, y_dev + BB * DD, y_dev + 2 * BB * DD }};
        GemmArgs ga;
        ga.src[0] = Y;  ga.src[1] = Y;
        ga.wtsel[0] = 2; ga.wtsel[1] = 2;
        k_gemm12<<<dim3(24, 4, 4), 128>>>(ga);
    }

    // Stage 4: out = p0..p3 + fc_b + y
    k_reduce2<<<192, 256>>>(fc_b, out);
}

// round 14
// speedup vs baseline: 1.1487x; 1.0439x over previous
#include <cuda_runtime.h>

#define DD 512
#define BB 128
#define EPSF 1e-5f
#define LOG2E_F 1.4426950408889634f
#define TJ 32
#define MATSZ (384 * 512)

// scratch (static device memory — no allocations)
__device__ float g_y [3 * BB * DD];
__device__ float g_wt[3 * DD * DD];      // k-major weights: [mat][k][m]
__device__ float g_part[16 * MATSZ];     // K-split partials (stage1: 16, fc: 8 reused)

struct Ptr3 { const float* p[3]; };

__device__ __forceinline__ float ex2f(float x) {
    float y;
    asm("ex2.approx.ftz.f32 %0, %1;" : "=f"(y) : "f"(x));
    return y;
}

// ===================== transpose weights: g_wt[z][d][m] = W_z[m][d] =====================
__global__ void __launch_bounds__(256)
k_transpose(const float* __restrict__ W0, const float* __restrict__ W1,
            const float* __restrict__ W2)
{
    __shared__ float t[32][33];
    const float* W = (blockIdx.z == 0) ? W0 : (blockIdx.z == 1) ? W1 : W2;
    float* O = g_wt + (size_t)blockIdx.z * DD * DD;
    int x  = blockIdx.x * 32 + threadIdx.x;
    int y0 = blockIdx.y * 32;
    #pragma unroll
    for (int i = threadIdx.y; i < 32; i += 8)
        t[i][threadIdx.x] = W[(size_t)(y0 + i) * DD + x];
    __syncthreads();
    int xo  = blockIdx.y * 32 + threadIdx.x;
    int yo0 = blockIdx.x * 32;
    #pragma unroll
    for (int i = threadIdx.y; i < 32; i += 8)
        O[(size_t)(yo0 + i) * DD + xo] = t[threadIdx.x][i];
}

// ===================== GEMM vS: smem-only compute, K=64/block, high block count ==========
// g_part[z][row][col] = sum_{k in slice} src[row][k] * Wt[k][col]
// block 128 thr; tile 32r x 64c; thread tile 4r x 4c.
// grid: (12 rowtiles, 8 coltiles, nmat * 8 ksplits)
struct GS {
    Ptr3 src[2];
    int wtsel[2];
};

#define SST 68

template <int NKS>
__global__ void __launch_bounds__(128)
k_gemmS(GS a)
{
    __shared__ __align__(16) float sS[32][SST];   // [row][k]  8.5 KB
    __shared__ __align__(16) float sW[64][SST];   // [k][col] 17 KB

    int tid = threadIdx.x;
    int rt = blockIdx.x, ct = blockIdx.y, z = blockIdx.z;
    int mat = z / NKS, ks = z % NKS;
    int r0 = rt * 32, c0 = ct * 64, k0 = ks * 64;

    const float* src = a.src[mat].p[r0 >> 7] + (size_t)(r0 & 127) * DD;
    const float* wt  = g_wt + (size_t)a.wtsel[mat] * DD * DD + (size_t)k0 * DD + c0;

    // stage src slice: 32 rows x 64 k (independent coalesced LDG.128s)
    #pragma unroll
    for (int it = 0; it < 4; it++) {
        int idx = it * 128 + tid;
        int row = idx >> 4, q = idx & 15;
        float4 v = *(const float4*)(src + (size_t)row * DD + k0 + q * 4);
        *(float4*)&sS[row][q * 4] = v;
    }
    // stage weight slice: 64 k x 64 c (independent coalesced LDG.128s)
    #pragma unroll
    for (int it = 0; it < 8; it++) {
        int idx = it * 128 + tid;
        int k = idx >> 4, q = idx & 15;
        float4 w = *(const float4*)(wt + (size_t)k * DD + q * 4);
        *(float4*)&sW[k][q * 4] = w;
    }
    __syncthreads();

    int c4 = tid & 15;     // 16 col-quads -> 64 cols
    int rg = tid >> 4;     // 8 row-groups of 4 rows

    float4 acc[4];
    #pragma unroll
    for (int r = 0; r < 4; r++) acc[r] = make_float4(0.f, 0.f, 0.f, 0.f);

    const float* s0 = &sS[4 * rg + 0][0];
    const float* s1 = &sS[4 * rg + 1][0];
    const float* s2 = &sS[4 * rg + 2][0];
    const float* s3 = &sS[4 * rg + 3][0];

    #pragma unroll 8
    for (int k = 0; k < 64; k++) {
        float4 w = *(const float4*)&sW[k][c4 * 4];
        float a0 = s0[k], a1 = s1[k], a2 = s2[k], a3 = s3[k];
        acc[0].x = fmaf(a0, w.x, acc[0].x);
        acc[0].y = fmaf(a0, w.y, acc[0].y);
        acc[0].z = fmaf(a0, w.z, acc[0].z);
        acc[0].w = fmaf(a0, w.w, acc[0].w);
        acc[1].x = fmaf(a1, w.x, acc[1].x);
        acc[1].y = fmaf(a1, w.y, acc[1].y);
        acc[1].z = fmaf(a1, w.z, acc[1].z);
        acc[1].w = fmaf(a1, w.w, acc[1].w);
        acc[2].x = fmaf(a2, w.x, acc[2].x);
        acc[2].y = fmaf(a2, w.y, acc[2].y);
        acc[2].z = fmaf(a2, w.z, acc[2].z);
        acc[2].w = fmaf(a2, w.w, acc[2].w);
        acc[3].x = fmaf(a3, w.x, acc[3].x);
        acc[3].y = fmaf(a3, w.y, acc[3].y);
        acc[3].z = fmaf(a3, w.z, acc[3].z);
        acc[3].w = fmaf(a3, w.w, acc[3].w);
    }

    float* outp = g_part + (size_t)z * MATSZ;
    #pragma unroll
    for (int r = 0; r < 4; r++) {
        int row = r0 + 4 * rg + r;
        *(float4*)(outp + (size_t)row * DD + c0 + c4 * 4) = acc[r];
    }
}

// ===================== fc final reduce: out = p0..p7 + fc_b + y (float4) =====================
__global__ void __launch_bounds__(256)
k_reduce2(const float* __restrict__ fcb, float* __restrict__ out)
{
    int idx = blockIdx.x * 256 + threadIdx.x;        // float4 index
    size_t i = (size_t)idx * 4;
    int col = (idx & 127) * 4;
    float4 s = *(const float4*)(g_part + i);
    #pragma unroll
    for (int q = 1; q < 8; q++) {
        float4 v = *(const float4*)(g_part + (size_t)q * MATSZ + i);
        s.x += v.x; s.y += v.y; s.z += v.z; s.w += v.w;
    }
    float4 bb = *(const float4*)(fcb + col);
    float4 yy = *(const float4*)(g_y + i);
    s.x += bb.x + yy.x;
    s.y += bb.y + yy.y;
    s.z += bb.z + yy.z;
    s.w += bb.w + yy.w;
    *(float4*)(out + i) = s;
}

// ---- block reductions over 512 threads (16 warps) ----
__device__ __forceinline__ float blockReduceSum(float v, float* red) {
    int tid = threadIdx.x, lane = tid & 31, wid = tid >> 5;
    #pragma unroll
    for (int o = 16; o > 0; o >>= 1) v += __shfl_down_sync(0xffffffffu, v, o);
    if (lane == 0) red[wid] = v;
    __syncthreads();
    if (wid == 0) {
        float x = (lane < 16) ? red[lane] : 0.0f;
        #pragma unroll
        for (int o = 8; o > 0; o >>= 1) x += __shfl_down_sync(0xffffffffu, x, o);
        if (lane == 0) red[0] = x;
    }
    __syncthreads();
    float r = red[0];
    __syncthreads();
    return r;
}

__device__ __forceinline__ float blockReduceMax(float v, float* red) {
    int tid = threadIdx.x, lane = tid & 31, wid = tid >> 5;
    #pragma unroll
    for (int o = 16; o > 0; o >>= 1) v = fmaxf(v, __shfl_down_sync(0xffffffffu, v, o));
    if (lane == 0) red[wid] = v;
    __syncthreads();
    if (wid == 0) {
        float x = (lane < 16) ? red[lane] : -3.4e38f;
        #pragma unroll
        for (int o = 8; o > 0; o >>= 1) x = fmaxf(x, __shfl_down_sync(0xffffffffu, x, o));
        if (lane == 0) red[0] = x;
    }
    __syncthreads();
    float r = red[0];
    __syncthreads();
    return r;
}

__device__ __forceinline__ float blockReduceMin(float v, float* red) {
    int tid = threadIdx.x, lane = tid & 31, wid = tid >> 5;
    #pragma unroll
    for (int o = 16; o > 0; o >>= 1) v = fminf(v, __shfl_down_sync(0xffffffffu, v, o));
    if (lane == 0) red[wid] = v;
    __syncthreads();
    if (wid == 0) {
        float x = (lane < 16) ? red[lane] : 3.4e38f;
        #pragma unroll
        for (int o = 8; o > 0; o >>= 1) x = fminf(x, __shfl_down_sync(0xffffffffu, x, o));
        if (lane == 0) red[0] = x;
    }
    __syncthreads();
    float r = red[0];
    __syncthreads();
    return r;
}

// ---- main fused kernel: one block per (batch, channel) ----
// Folds the stage-1 K-split-8 reduction + bias into its loads.
__global__ void __launch_bounds__(512)
k_main(Ptr3 x, Ptr3 h, Ptr3 kq,
       const float* __restrict__ bk, const float* __restrict__ bq,
       const float* __restrict__ kn_g, const float* __restrict__ kn_b,
       const float* __restrict__ norm_g, const float* __restrict__ norm_b)
{
    extern __shared__ float E[];              // [512][TJ+1]
    __shared__ float s_s[DD], s_u2[DD], s_v[DD];
    __shared__ float Zpart[16][TJ + 1];
    __shared__ float coefT[TJ];
    __shared__ float red[32];

    const int ESTR = TJ + 1;

    int b = blockIdx.x, c = blockIdx.y, tid = threadIdx.x;
    int row = c * BB + b;
    size_t ri = (size_t)row * DD + tid;

    float wk = bk[tid];
    float wq = bq[tid];
    #pragma unroll
    for (int q = 0; q < 8; q++) wk += g_part[(size_t)q * MATSZ + ri];
    #pragma unroll
    for (int q = 8; q < 16; q++) wq += g_part[(size_t)q * MATSZ + ri];

    float kv = h.p[c][(size_t)b * DD + tid];
    float qv = kq.p[c][(size_t)b * DD + tid];
    float vv = x.p[c][(size_t)b * DD + tid];

    const float inv_d = 1.0f / (float)DD;
    float mu_wk  = blockReduceSum(wk, red) * inv_d;
    float dk     = wk - mu_wk;
    float var_wk = blockReduceSum(dk * dk, red) * inv_d;
    float mu_wq  = blockReduceSum(wq, red) * inv_d;
    float dq     = wq - mu_wq;
    float var_wq = blockReduceSum(dq * dq, red) * inv_d;

    float gg = kn_g[tid];
    float cb = kn_b[tid];

    float si = kv * rsqrtf(kv * kv * var_wk + EPSF);
    float ti = qv * rsqrtf(qv * qv * var_wq + EPSF);
    float Ai = dk * gg;
    float Bi = dq * gg;

    float P    = blockReduceSum(Ai * ti, red);
    float Qs   = blockReduceSum(Ai, red);
    float smax = blockReduceMax(si, red);
    float smin = blockReduceMin(si, red);

    float u2 = (P * Bi + Qs * cb) * LOG2E_F;
    s_s[tid]  = si;
    s_u2[tid] = u2;
    s_v[tid]  = vv;
    __syncthreads();

    int g = tid >> 5;
    int j = tid & 31;

    float acc = 0.0f;

    #pragma unroll 1
    for (int jt = 0; jt < DD; jt += TJ) {
        float u2j = s_u2[jt + j];
        float m2j = fmaxf(u2j * smax, u2j * smin);
        float Zl = 0.0f;

        float* Ecol = E + (size_t)(g * 32) * ESTR + j;
        const float* sbase = s_s + g * 32;
        #pragma unroll
        for (int i4 = 0; i4 < 32; i4 += 4) {
            float4 s4 = *(const float4*)(sbase + i4);
            float e0 = ex2f(fmaf(s4.x, u2j, -m2j));
            float e1 = ex2f(fmaf(s4.y, u2j, -m2j));
            float e2 = ex2f(fmaf(s4.z, u2j, -m2j));
            float e3 = ex2f(fmaf(s4.w, u2j, -m2j));
            Zl += (e0 + e1) + (e2 + e3);
            Ecol[(i4 + 0) * ESTR] = e0;
            Ecol[(i4 + 1) * ESTR] = e1;
            Ecol[(i4 + 2) * ESTR] = e2;
            Ecol[(i4 + 3) * ESTR] = e3;
        }
        Zpart[g][j] = Zl;
        __syncthreads();

        if (tid < TJ) {
            float zt = 0.0f;
            #pragma unroll
            for (int w = 0; w < 16; w++) zt += Zpart[w][tid];
            coefT[tid] = s_v[jt + tid] / zt;
        }
        __syncthreads();

        const float* Erow = E + (size_t)tid * ESTR;
        #pragma unroll
        for (int jj = 0; jj < TJ; jj += 4) {
            float c0 = coefT[jj + 0], c1 = coefT[jj + 1];
            float c2 = coefT[jj + 2], c3 = coefT[jj + 3];
            acc = fmaf(c0, Erow[jj + 0], acc);
            acc = fmaf(c1, Erow[jj + 1], acc);
            acc = fmaf(c2, Erow[jj + 2], acc);
            acc = fmaf(c3, Erow[jj + 3], acc);
        }
        __syncthreads();
    }

    float y     = acc + vv;
    float mu_y  = blockReduceSum(y, red) * inv_d;
    float dy    = y - mu_y;
    float var_y = blockReduceSum(dy * dy, red) * inv_d;
    float yn    = dy * rsqrtf(var_y + EPSF) * norm_g[tid] + norm_b[tid];

    g_y[(size_t)row * DD + tid] = yn;
}

extern "C" void kernel_launch(void* const* d_in, const int* in_sizes, int n_in,
                              void* d_out, int out_size)
{
    (void)in_sizes; (void)n_in; (void)out_size;
    const float* r    = (const float*)d_in[0];
    const float* g    = (const float*)d_in[1];
    const float* b    = (const float*)d_in[2];
    const float* h_r  = (const float*)d_in[3];
    const float* h_g  = (const float*)d_in[4];
    const float* h_b  = (const float*)d_in[5];
    const float* k_r  = (const float*)d_in[6];
    const float* k_g  = (const float*)d_in[7];
    const float* k_b  = (const float*)d_in[8];
    const float* Wk   = (const float*)d_in[9];
    const float* bk   = (const float*)d_in[10];
    const float* Wq   = (const float*)d_in[11];
    const float* bq   = (const float*)d_in[12];
    const float* kn_g = (const float*)d_in[13];
    const float* kn_b = (const float*)d_in[14];
    const float* norm_g = (const float*)d_in[15];
    const float* norm_b = (const float*)d_in[16];
    const float* fc_w = (const float*)d_in[17];
    const float* fc_b = (const float*)d_in[18];
    float* out = (float*)d_out;

    Ptr3 X  = {{ r,   g,   b   }};
    Ptr3 H  = {{ h_r, h_g, h_b }};
    Ptr3 KQ = {{ k_r, k_g, k_b }};

    const size_t E_BYTES = (size_t)DD * (TJ + 1) * sizeof(float);

    static float* y_dev  = nullptr;
    if (y_dev == nullptr) {
        void* p = nullptr;
        cudaGetSymbolAddress(&p, g_y);  y_dev = (float*)p;
        cudaFuncSetAttribute(k_main, cudaFuncAttributeMaxDynamicSharedMemorySize,
                             (int)E_BYTES);
    }

    // Stage 0: transpose weights -> g_wt (k-major)
    k_transpose<<<dim3(16, 16, 3), dim3(32, 8)>>>(Wk, Wq, fc_w);

    // Stage 1: w_k / w_q partials (K-split 8 per matrix), z = mat*8 + ks
    {
        GS a;
        a.src[0] = H;  a.src[1] = KQ;
        a.wtsel[0] = 0; a.wtsel[1] = 1;
        k_gemmS<8><<<dim3(12, 8, 16), 128>>>(a);
    }

    // Stage 2: folds stage-1 partials + bias; attention + residual + LN -> g_y
    k_main<<<dim3(BB, 3), 512, E_BYTES>>>(X, H, KQ, bk, bq,
                                          kn_g, kn_b, norm_g, norm_b);

    // Stage 3: fc partials (K-split 8), src = g_y
    {
        Ptr3 Y = {{ y_dev, y_dev + BB * DD, y_dev + 2 * BB * DD }};
        GS a;
        a.src[0] = Y;  a.src[1] = Y;
        a.wtsel[0] = 2; a.wtsel[1] = 2;
        k_gemmS<8><<<dim3(12, 8, 8), 128>>>(a);
    }

    // Stage 4: out = p0..p7 + fc_b + y
    k_reduce2<<<192, 256>>>(fc_b, out);
}